// round 7
// baseline (speedup 1.0000x reference)
#include <cuda_runtime.h>
#include <cuda_fp16.h>
#include <math.h>
#include <stdint.h>

#define MTOK 65536   // 8 * 8192 tokens
#define D    128
#define HDIM 256
#define NLAYER 16

// ======================= device global scratch ==============================
__device__ __half g_xn [(size_t)MTOK * D];       // LN'd mixing output (fp16)
__device__ __half g_hid[(size_t)MTOK * HDIM];    // GELU hidden (fp16)
__device__ float  g_blk[4][(size_t)MTOK * D];    // fp32 accumulators
__device__ __half g_blkh[4][(size_t)MTOK * D];   // fp16 mirrors for mix reads
__device__ __half g_embh[(size_t)MTOK * D];      // fp16 embedding mirror
__device__ __half g_w1t[NLAYER * HDIM * D];      // [l][n=256][k=128]
__device__ __half g_w2t[NLAYER * D * HDIM];      // [l][n=128][k=256]

// ======================= small helpers ======================================
__device__ __forceinline__ uint32_t smem_u32(const void* p) {
    uint32_t a;
    asm("{ .reg .u64 t; cvta.to.shared.u64 t, %1; cvt.u32.u64 %0, t; }" : "=r"(a) : "l"(p));
    return a;
}
__device__ __forceinline__ uint32_t pack_h2(__half a, __half b) {
    return (uint32_t)__half_as_ushort(a) | ((uint32_t)__half_as_ushort(b) << 16);
}
__device__ __forceinline__ void ldm4(uint32_t* r, uint32_t addr) {
    asm volatile("ldmatrix.sync.aligned.m8n8.x4.shared.b16 {%0,%1,%2,%3}, [%4];"
                 : "=r"(r[0]), "=r"(r[1]), "=r"(r[2]), "=r"(r[3]) : "r"(addr));
}
__device__ __forceinline__ void mma16816(float* c, const uint32_t* a,
                                         uint32_t b0, uint32_t b1) {
    asm volatile("mma.sync.aligned.m16n8k16.row.col.f32.f16.f16.f32 "
                 "{%0,%1,%2,%3}, {%4,%5,%6,%7}, {%8,%9}, {%0,%1,%2,%3};"
                 : "+f"(c[0]), "+f"(c[1]), "+f"(c[2]), "+f"(c[3])
                 : "r"(a[0]), "r"(a[1]), "r"(a[2]), "r"(a[3]), "r"(b0), "r"(b1));
}
__device__ __forceinline__ void cp16(uint32_t dst, const void* src) {
    asm volatile("cp.async.cg.shared.global [%0], [%1], 16;" :: "r"(dst), "l"(src));
}
#define CP_COMMIT() asm volatile("cp.async.commit_group;" ::: "memory")
#define CP_WAIT0()  asm volatile("cp.async.wait_group 0;"  ::: "memory")

// ======================= fp16 mma GEMM ======================================
// CTA 128x128, 8 warps (4m x 2n), warp tile 32x64.
// EPI: 0 = bias+GELU -> fp16 (stride HDIM)
//      1 = bias -> fp32 + fp16 mirror      2 = bias + acc fp32 + fp16 mirror
#define SROWA 136

template<int EPI, int K>
__global__ __launch_bounds__(256, 2)
void mma_gemm(const __half* __restrict__ A, const __half* __restrict__ B,
              const float* __restrict__ bias,
              __half* __restrict__ Oh, float* __restrict__ Cf,
              __half* __restrict__ Ch) {
    constexpr int SROWB = (K == 128) ? 136 : 264;
    extern __shared__ char smem[];
    __shared__ float sbias[128];
    __half* sA = (__half*)smem;
    __half* sB = sA + 128 * SROWA;

    const int tid  = threadIdx.x;
    const int wid  = tid >> 5;
    const int lane = tid & 31;
    const int bn   = blockIdx.x * 128;
    const int bm   = blockIdx.y * 128;
    const int wm   = (wid >> 1) * 32;
    const int wn   = (wid & 1) * 64;

    const uint32_t sbA = smem_u32(sA);
    const uint32_t sbB = smem_u32(sB);
    const int frow = tid >> 1;

    // ---- prologue: all of B, A chunk 0, bias ----
    {
        if (K == 128) {
            int col = (tid & 1) * 64;
            const char* src = (const char*)(B + (size_t)(bn + frow) * K + col);
            uint32_t dst = sbB + (uint32_t)(frow * SROWB + col) * 2;
#pragma unroll
            for (int q = 0; q < 8; q++) cp16(dst + q * 16, src + q * 16);
        } else {
            int col = (tid & 1) * 128;
            const char* src = (const char*)(B + (size_t)(bn + frow) * K + col);
            uint32_t dst = sbB + (uint32_t)(frow * SROWB + col) * 2;
#pragma unroll
            for (int q = 0; q < 16; q++) cp16(dst + q * 16, src + q * 16);
        }
        {
            int col = (tid & 1) * 64;
            const char* src = (const char*)(A + (size_t)(bm + frow) * K + col);
            uint32_t dst = sbA + (uint32_t)(frow * SROWA + col) * 2;
#pragma unroll
            for (int q = 0; q < 8; q++) cp16(dst + q * 16, src + q * 16);
        }
        if (tid < 128) sbias[tid] = bias[bn + tid];
        CP_COMMIT();
    }

    float acc[2][8][4];
#pragma unroll
    for (int i = 0; i < 2; i++)
#pragma unroll
        for (int j = 0; j < 8; j++)
#pragma unroll
            for (int q = 0; q < 4; q++) acc[i][j][q] = 0.f;

    const int a_r = (lane & 15);
    const int a_k = (lane >> 4) << 3;
    const int b_r = (lane & 7) + ((lane >> 4) << 3);
    const int b_k = ((lane >> 3) & 1) << 3;

    CP_WAIT0();
    __syncthreads();

#pragma unroll
    for (int kc = 0; kc < K; kc += 128) {
        if (kc) {
            __syncthreads();
            int col = (tid & 1) * 64;
            const char* src = (const char*)(A + (size_t)(bm + frow) * K + kc + col);
            uint32_t dst = sbA + (uint32_t)(frow * SROWA + col) * 2;
#pragma unroll
            for (int q = 0; q < 8; q++) cp16(dst + q * 16, src + q * 16);
            CP_COMMIT();
            CP_WAIT0();
            __syncthreads();
        }
#pragma unroll
        for (int k16 = 0; k16 < 128; k16 += 16) {
            uint32_t a[2][4];
#pragma unroll
            for (int mi = 0; mi < 2; mi++)
                ldm4(a[mi], sbA + (uint32_t)((wm + mi * 16 + a_r) * (SROWA * 2) + (k16 + a_k) * 2));
            // interleave: one B ldmatrix feeds 4 MMAs; only 4 B regs live
#pragma unroll
            for (int np = 0; np < 4; np++) {
                uint32_t t[4];
                ldm4(t, sbB + (uint32_t)((wn + np * 16 + b_r) * (SROWB * 2) + (kc + k16 + b_k) * 2));
                mma16816(acc[0][2 * np],     a[0], t[0], t[1]);
                mma16816(acc[0][2 * np + 1], a[0], t[2], t[3]);
                mma16816(acc[1][2 * np],     a[1], t[0], t[1]);
                mma16816(acc[1][2 * np + 1], a[1], t[2], t[3]);
            }
        }
    }

    // ---------------- epilogue ----------------
    const int g  = lane >> 2;
    const int t4 = lane & 3;
#pragma unroll
    for (int mi = 0; mi < 2; mi++) {
#pragma unroll
        for (int nj = 0; nj < 8; nj++) {
            int colL = wn + nj * 8 + 2 * t4;
            float b0 = sbias[colL], b1 = sbias[colL + 1];
#pragma unroll
            for (int h = 0; h < 2; h++) {
                int row = bm + wm + mi * 16 + g + h * 8;
                float x0 = acc[mi][nj][2 * h]     + b0;
                float x1 = acc[mi][nj][2 * h + 1] + b1;
                if (EPI == 0) {
                    float y0 = 0.5f * x0 * (1.0f + erff(x0 * 0.70710678118654752f));
                    float y1 = 0.5f * x1 * (1.0f + erff(x1 * 0.70710678118654752f));
                    *(uint32_t*)(Oh + (size_t)row * HDIM + bn + colL) =
                        pack_h2(__float2half_rn(y0), __float2half_rn(y1));
                } else {
                    float* cp = Cf + (size_t)row * D + bn + colL;
                    if (EPI == 2) {
                        float2 o = *(const float2*)cp;
                        x0 += o.x; x1 += o.y;
                    }
                    float2 v = {x0, x1};
                    *(float2*)cp = v;
                    *(uint32_t*)(Ch + (size_t)row * D + bn + colL) =
                        pack_h2(__float2half_rn(x0), __float2half_rn(x1));
                }
            }
        }
    }
}

// ======================= prep: weights transpose + emb fp16 =================
__global__ void prep_all(const float* __restrict__ W1, const float* __restrict__ W2,
                         const float* __restrict__ emb) {
    const size_t T1 = (size_t)NLAYER * HDIM * D;
    const size_t T2 = (size_t)NLAYER * D * HDIM;
    const size_t T3 = (size_t)MTOK * D;
    for (size_t i = (size_t)blockIdx.x * blockDim.x + threadIdx.x; i < T1 + T2 + T3;
         i += (size_t)gridDim.x * blockDim.x) {
        if (i < T1) {
            size_t l = i / (HDIM * D), r = i % (HDIM * D);
            size_t n = r / D, k = r % D;
            g_w1t[i] = __float2half_rn(W1[(l * D + k) * HDIM + n]);
        } else if (i < T1 + T2) {
            size_t j = i - T1;
            size_t l = j / (D * HDIM), r = j % (D * HDIM);
            size_t n = r / HDIM, k = r % HDIM;
            g_w2t[j] = __float2half_rn(W2[(l * HDIM + k) * D + n]);
        } else {
            size_t j = i - T1 - T2;
            g_embh[j] = __float2half_rn(emb[j]);
        }
    }
}

// ======================= mixing kernel (fp16 sources) =======================
// 16 lanes per token, 8 halves per lane.
struct SrcPtrsH { const __half* p[5]; };

__device__ __forceinline__ float wsum16(float v) {
#pragma unroll
    for (int o = 8; o > 0; o >>= 1) v += __shfl_xor_sync(0xffffffffu, v, o);
    return v;
}

template<bool WRITE_H>
__global__ __launch_bounds__(256)
void mix_kernel(SrcPtrsH src, int n, const float* __restrict__ wrow,
                const float* __restrict__ lg, const float* __restrict__ lb,
                float* __restrict__ outp, __half* __restrict__ outh) {
    int tok  = blockIdx.x * 16 + (threadIdx.x >> 4);
    int l16  = threadIdx.x & 15;
    int base = tok * D + l16 * 8;

    float4 w0 = *(const float4*)(wrow + l16 * 8);
    float4 w1 = *(const float4*)(wrow + l16 * 8 + 4);
    float wv[8] = {w0.x, w0.y, w0.z, w0.w, w1.x, w1.y, w1.z, w1.w};

    float v[5][8];
    float lgt[5];
#pragma unroll
    for (int i = 0; i < 5; i++) {
        if (i < n) {
            uint4 raw = *(const uint4*)(src.p[i] + base);   // 8 halves
            const uint32_t* pr = (const uint32_t*)&raw;
#pragma unroll
            for (int q = 0; q < 4; q++) {
                float2 f = __half22float2(*(const __half2*)&pr[q]);
                v[i][2 * q] = f.x; v[i][2 * q + 1] = f.y;
            }
            float ss = 0.f, dt = 0.f;
#pragma unroll
            for (int j = 0; j < 8; j++) { ss += v[i][j] * v[i][j]; dt += wv[j] * v[i][j]; }
            ss = wsum16(ss);
            dt = wsum16(dt);
            lgt[i] = dt * rsqrtf(ss * (1.0f / D) + 1e-8f);
        }
    }

    float mx = -1e30f;
#pragma unroll
    for (int i = 0; i < 5; i++) if (i < n) mx = fmaxf(mx, lgt[i]);
    float se = 0.f;
#pragma unroll
    for (int i = 0; i < 5; i++) if (i < n) { lgt[i] = expf(lgt[i] - mx); se += lgt[i]; }
    float inv = 1.f / se;

    float h[8];
#pragma unroll
    for (int j = 0; j < 8; j++) h[j] = 0.f;
#pragma unroll
    for (int i = 0; i < 5; i++) if (i < n) {
        float wt = lgt[i] * inv;
#pragma unroll
        for (int j = 0; j < 8; j++) h[j] += wt * v[i][j];
    }

    if (WRITE_H) {
        float4 o0 = {h[0], h[1], h[2], h[3]};
        float4 o1 = {h[4], h[5], h[6], h[7]};
        *(float4*)(outp + base) = o0;
        *(float4*)(outp + base + 4) = o1;
    } else {
        float s = 0.f;
#pragma unroll
        for (int j = 0; j < 8; j++) s += h[j];
        float mu = wsum16(s) * (1.0f / D);
        float vs = 0.f;
#pragma unroll
        for (int j = 0; j < 8; j++) { float d = h[j] - mu; vs += d * d; }
        float var = wsum16(vs) * (1.0f / D);
        float r = rsqrtf(var + 1e-5f);
        float4 g0 = *(const float4*)(lg + l16 * 8);
        float4 g1 = *(const float4*)(lg + l16 * 8 + 4);
        float4 b0 = *(const float4*)(lb + l16 * 8);
        float4 b1 = *(const float4*)(lb + l16 * 8 + 4);
        float gg[8] = {g0.x, g0.y, g0.z, g0.w, g1.x, g1.y, g1.z, g1.w};
        float bb[8] = {b0.x, b0.y, b0.z, b0.w, b1.x, b1.y, b1.z, b1.w};
        uint32_t pk[4];
#pragma unroll
        for (int q = 0; q < 4; q++) {
            float o0 = (h[2*q]   - mu) * r * gg[2*q]   + bb[2*q];
            float o1 = (h[2*q+1] - mu) * r * gg[2*q+1] + bb[2*q+1];
            pk[q] = pack_h2(__float2half_rn(o0), __float2half_rn(o1));
        }
        *(uint2*)(outh + base)     = make_uint2(pk[0], pk[1]);
        *(uint2*)(outh + base + 4) = make_uint2(pk[2], pk[3]);
    }
}

// ======================= host orchestration =================================
#define SMEM1 (128 * SROWA * 2 + 128 * 136 * 2)   // 69632
#define SMEM2 (128 * SROWA * 2 + 128 * 264 * 2)   // 102400

extern "C" void kernel_launch(void* const* d_in, const int* in_sizes, int n_in,
                              void* d_out, int out_size) {
    const float* emb  = (const float*)d_in[0];
    const float* w    = (const float*)d_in[1];
    const float* ln_g = (const float*)d_in[2];
    const float* ln_b = (const float*)d_in[3];
    const float* W1   = (const float*)d_in[4];
    const float* b1   = (const float*)d_in[5];
    const float* W2   = (const float*)d_in[6];
    const float* b2   = (const float*)d_in[7];
    float* out = (float*)d_out;

    __half *xn, *hid, *w1t, *w2t, *embh, *blkh;
    float* blk;
    cudaGetSymbolAddress((void**)&xn,   g_xn);
    cudaGetSymbolAddress((void**)&hid,  g_hid);
    cudaGetSymbolAddress((void**)&blk,  g_blk);
    cudaGetSymbolAddress((void**)&blkh, g_blkh);
    cudaGetSymbolAddress((void**)&embh, g_embh);
    cudaGetSymbolAddress((void**)&w1t,  g_w1t);
    cudaGetSymbolAddress((void**)&w2t,  g_w2t);

    cudaFuncSetAttribute(mma_gemm<0,128>, cudaFuncAttributeMaxDynamicSharedMemorySize, SMEM1);
    cudaFuncSetAttribute(mma_gemm<1,256>, cudaFuncAttributeMaxDynamicSharedMemorySize, SMEM2);
    cudaFuncSetAttribute(mma_gemm<2,256>, cudaFuncAttributeMaxDynamicSharedMemorySize, SMEM2);

    prep_all<<<512, 256>>>(W1, W2, emb);

    for (int l = 0; l < NLAYER; l++) {
        int  grp        = l >> 2;
        bool hasPartial = (l & 3) != 0;

        SrcPtrsH sp;
        int n = 0;
        sp.p[n++] = embh;
        for (int i = 0; i < grp; i++) sp.p[n++] = blkh + (size_t)i * MTOK * D;
        if (hasPartial) sp.p[n++] = blkh + (size_t)grp * MTOK * D;
        for (int i = n; i < 5; i++) sp.p[i] = embh;

        if (l == NLAYER - 1) {
            mix_kernel<true><<<MTOK / 16, 256>>>(sp, n, w + l * D, nullptr, nullptr,
                                                 out, nullptr);
        } else {
            mix_kernel<false><<<MTOK / 16, 256>>>(sp, n, w + l * D,
                                                  ln_g + l * D, ln_b + l * D,
                                                  nullptr, xn);
            dim3 g1(2, MTOK / 128);
            mma_gemm<0,128><<<g1, 256, SMEM1>>>(
                xn, w1t + (size_t)l * HDIM * D, b1 + (size_t)l * HDIM, hid, nullptr, nullptr);
            dim3 g2(1, MTOK / 128);
            float* dst  = blk  + (size_t)grp * MTOK * D;
            __half* dsh = blkh + (size_t)grp * MTOK * D;
            if (hasPartial)
                mma_gemm<2,256><<<g2, 256, SMEM2>>>(
                    hid, w2t + (size_t)l * D * HDIM, b2 + (size_t)l * D, nullptr, dst, dsh);
            else
                mma_gemm<1,256><<<g2, 256, SMEM2>>>(
                    hid, w2t + (size_t)l * D * HDIM, b2 + (size_t)l * D, nullptr, dst, dsh);
        }
    }
}

// round 8
// speedup vs baseline: 1.1000x; 1.1000x over previous
#include <cuda_runtime.h>
#include <cuda_fp16.h>
#include <math.h>
#include <stdint.h>

#define MTOK 65536   // 8 * 8192 tokens
#define D    128
#define HDIM 256
#define NLAYER 16
#define TTILE 128            // tokens per CTA
#define NCTA  (MTOK / TTILE) // 512
#define THREADS 512

// ======================= device global scratch ==============================
__device__ __half g_blocks[5][(size_t)MTOK * D];  // [0]=emb fp16, [1..4]=committed
__device__ __half g_w1t[NLAYER * HDIM * D];       // [l][n=256][k=128]
__device__ __half g_w2t[NLAYER * D * HDIM];       // [l][n=128][k=256]

// ======================= helpers ============================================
__device__ __forceinline__ uint32_t smem_u32(const void* p) {
    uint32_t a;
    asm("{ .reg .u64 t; cvta.to.shared.u64 t, %1; cvt.u32.u64 %0, t; }" : "=r"(a) : "l"(p));
    return a;
}
__device__ __forceinline__ uint32_t pack_h2(__half a, __half b) {
    return (uint32_t)__half_as_ushort(a) | ((uint32_t)__half_as_ushort(b) << 16);
}
__device__ __forceinline__ void ldm4(uint32_t* r, uint32_t addr) {
    asm volatile("ldmatrix.sync.aligned.m8n8.x4.shared.b16 {%0,%1,%2,%3}, [%4];"
                 : "=r"(r[0]), "=r"(r[1]), "=r"(r[2]), "=r"(r[3]) : "r"(addr));
}
__device__ __forceinline__ void mma16816(float* c, const uint32_t* a,
                                         uint32_t b0, uint32_t b1) {
    asm volatile("mma.sync.aligned.m16n8k16.row.col.f32.f16.f16.f32 "
                 "{%0,%1,%2,%3}, {%4,%5,%6,%7}, {%8,%9}, {%0,%1,%2,%3};"
                 : "+f"(c[0]), "+f"(c[1]), "+f"(c[2]), "+f"(c[3])
                 : "r"(a[0]), "r"(a[1]), "r"(a[2]), "r"(a[3]), "r"(b0), "r"(b1));
}
__device__ __forceinline__ void cp16(uint32_t dst, const void* src) {
    asm volatile("cp.async.cg.shared.global [%0], [%1], 16;" :: "r"(dst), "l"(src));
}
#define CP_COMMIT() asm volatile("cp.async.commit_group;" ::: "memory")
#define CP_WAIT0()  asm volatile("cp.async.wait_group 0;"  ::: "memory")

__device__ __forceinline__ float wsum16(float v) {
#pragma unroll
    for (int o = 8; o > 0; o >>= 1) v += __shfl_xor_sync(0xffffffffu, v, o);
    return v;
}

// ======================= smem layout ========================================
#define SP_PART 0                      // fp32 [128][128]           65536
#define SP_XN   65536                  // half [128][136]           34816
#define SP_HID  100352                 // half [128][264]           67584
#define SP_W    167936                 // half [128][136]           34816
#define SMEM_TOTAL 202752

// fill one 128x128-half weight chunk into sW (stride 136), rows from src with
// rowStride halves. 512 threads: 4 threads/row, 4x16B each.
__device__ __forceinline__ void fill_w(uint32_t sW, const __half* __restrict__ src,
                                       int rowStride, int tid) {
    int row = tid >> 2, q = tid & 3;
    const char* s = (const char*)(src + (size_t)row * rowStride) + q * 64;
    uint32_t d = sW + (uint32_t)(row * 136 + q * 32) * 2;
#pragma unroll
    for (int j = 0; j < 4; j++) cp16(d + j * 16, s + j * 16);
    CP_COMMIT();
}

// one 128x128 GEMM tile accumulation (8 k16 steps); A stride SRA (+ col off), B stride 136
template<int SRA>
__device__ __forceinline__ void gemm_tile(uint32_t sbA, int aOff, uint32_t sbB,
                                          float acc[2][4][4], int wm, int wn,
                                          int a_r, int a_k, int b_r, int b_k) {
#pragma unroll
    for (int k16 = 0; k16 < 128; k16 += 16) {
        uint32_t a[2][4];
#pragma unroll
        for (int mi = 0; mi < 2; mi++)
            ldm4(a[mi], sbA + (uint32_t)((wm + mi * 16 + a_r) * SRA + aOff + k16 + a_k) * 2);
#pragma unroll
        for (int np = 0; np < 2; np++) {
            uint32_t t[4];
            ldm4(t, sbB + (uint32_t)((wn + np * 16 + b_r) * 136 + k16 + b_k) * 2);
            mma16816(acc[0][2 * np],     a[0], t[0], t[1]);
            mma16816(acc[0][2 * np + 1], a[0], t[2], t[3]);
            mma16816(acc[1][2 * np],     a[1], t[0], t[1]);
            mma16816(acc[1][2 * np + 1], a[1], t[2], t[3]);
        }
    }
}

// ======================= fused whole-network kernel =========================
__global__ __launch_bounds__(THREADS, 1)
void fused_net(const float* __restrict__ w, const float* __restrict__ ln_g,
               const float* __restrict__ ln_b, const float* __restrict__ b1,
               const float* __restrict__ b2, float* __restrict__ out) {
    extern __shared__ char smem[];
    float*  sPart = (float*)(smem + SP_PART);
    __half* sXn   = (__half*)(smem + SP_XN);
    __half* sHid  = (__half*)(smem + SP_HID);
    const uint32_t sbPart = smem_u32(sPart);
    const uint32_t sbXn = smem_u32(sXn);
    const uint32_t sbHid = smem_u32(sHid);
    const uint32_t sbW = smem_u32(smem + SP_W);

    const int tid  = threadIdx.x;
    const int wid  = tid >> 5;
    const int lane = tid & 31;
    const int bm   = blockIdx.x * TTILE;

    // warp tiling: 16 warps = 4m x 4n, warp tile 32x32
    const int wm = (wid >> 2) * 32;
    const int wn = (wid & 3) * 32;
    const int a_r = (lane & 15);
    const int a_k = (lane >> 4) << 3;
    const int b_r = (lane & 7) + ((lane >> 4) << 3);
    const int b_k = ((lane >> 3) & 1) << 3;
    const int g  = lane >> 2;
    const int t4 = lane & 3;

    // mix coords: 16 lanes/token, 8 dims/lane, 32 tokens per pass
    const int mtok0 = tid >> 4;       // 0..31
    const int l16   = tid & 15;

    const __half* gb = &g_blocks[0][0];

    for (int l = 0; l < NLAYER; l++) {
        const int grp = l >> 2;
        const int hasPartial = (l & 3) != 0;
        const int nsg = 1 + grp;                 // gmem sources
        const __half* w1l = g_w1t + (size_t)l * HDIM * D;
        const __half* w2l = g_w2t + (size_t)l * D * HDIM;

        if (l < NLAYER - 1) fill_w(sbW, w1l, D, tid);   // prefetch W1 chunk0

        // ---------------- mix phase ----------------
        {
            const float* wrow = w + l * D;
            float wv[8], gg[8], bb[8];
            {
                float4 a0 = *(const float4*)(wrow + l16 * 8);
                float4 a1 = *(const float4*)(wrow + l16 * 8 + 4);
                wv[0]=a0.x; wv[1]=a0.y; wv[2]=a0.z; wv[3]=a0.w;
                wv[4]=a1.x; wv[5]=a1.y; wv[6]=a1.z; wv[7]=a1.w;
            }
            if (l < NLAYER - 1) {
                float4 a0 = *(const float4*)(ln_g + l * D + l16 * 8);
                float4 a1 = *(const float4*)(ln_g + l * D + l16 * 8 + 4);
                gg[0]=a0.x; gg[1]=a0.y; gg[2]=a0.z; gg[3]=a0.w;
                gg[4]=a1.x; gg[5]=a1.y; gg[6]=a1.z; gg[7]=a1.w;
                float4 c0 = *(const float4*)(ln_b + l * D + l16 * 8);
                float4 c1 = *(const float4*)(ln_b + l * D + l16 * 8 + 4);
                bb[0]=c0.x; bb[1]=c0.y; bb[2]=c0.z; bb[3]=c0.w;
                bb[4]=c1.x; bb[5]=c1.y; bb[6]=c1.z; bb[7]=c1.w;
            }
#pragma unroll 1
            for (int it = 0; it < 4; it++) {
                int tg = it * 32 + mtok0;        // local token
                float v[5][8];
                float lgt[5];
                int n = 0;
#pragma unroll
                for (int i = 0; i < 4; i++) {
                    if (i < nsg) {
                        uint4 raw = *(const uint4*)(gb + ((size_t)i * MTOK + bm + tg) * D + l16 * 8);
                        const uint32_t* pr = (const uint32_t*)&raw;
#pragma unroll
                        for (int q = 0; q < 4; q++) {
                            float2 f = __half22float2(*(const __half2*)&pr[q]);
                            v[i][2 * q] = f.x; v[i][2 * q + 1] = f.y;
                        }
                        n++;
                    }
                }
                if (hasPartial) {
                    const float* pp = sPart + tg * 128 + l16 * 8;
                    float4 p0 = *(const float4*)pp;
                    float4 p1 = *(const float4*)(pp + 4);
                    v[n][0]=p0.x; v[n][1]=p0.y; v[n][2]=p0.z; v[n][3]=p0.w;
                    v[n][4]=p1.x; v[n][5]=p1.y; v[n][6]=p1.z; v[n][7]=p1.w;
                    n++;
                }
#pragma unroll
                for (int i = 0; i < 5; i++) {
                    if (i < n) {
                        float ss = 0.f, dt = 0.f;
#pragma unroll
                        for (int j = 0; j < 8; j++) { ss += v[i][j]*v[i][j]; dt += wv[j]*v[i][j]; }
                        ss = wsum16(ss);
                        dt = wsum16(dt);
                        lgt[i] = dt * rsqrtf(ss * (1.0f / D) + 1e-8f);
                    }
                }
                float mx = -1e30f;
#pragma unroll
                for (int i = 0; i < 5; i++) if (i < n) mx = fmaxf(mx, lgt[i]);
                float se = 0.f;
#pragma unroll
                for (int i = 0; i < 5; i++) if (i < n) { lgt[i] = expf(lgt[i] - mx); se += lgt[i]; }
                float inv = 1.f / se;
                float h[8];
#pragma unroll
                for (int j = 0; j < 8; j++) h[j] = 0.f;
#pragma unroll
                for (int i = 0; i < 5; i++) if (i < n) {
                    float wt = lgt[i] * inv;
#pragma unroll
                    for (int j = 0; j < 8; j++) h[j] += wt * v[i][j];
                }

                if (l == NLAYER - 1) {
                    float* op = out + (size_t)(bm + tg) * D + l16 * 8;
                    float4 o0 = {h[0], h[1], h[2], h[3]};
                    float4 o1 = {h[4], h[5], h[6], h[7]};
                    *(float4*)op = o0;
                    *(float4*)(op + 4) = o1;
                } else {
                    float s = 0.f;
#pragma unroll
                    for (int j = 0; j < 8; j++) s += h[j];
                    float mu = wsum16(s) * (1.0f / D);
                    float vs = 0.f;
#pragma unroll
                    for (int j = 0; j < 8; j++) { float d0 = h[j] - mu; vs += d0 * d0; }
                    float var = wsum16(vs) * (1.0f / D);
                    float r = rsqrtf(var + 1e-5f);
                    uint32_t pk[4];
#pragma unroll
                    for (int q = 0; q < 4; q++) {
                        float o0 = (h[2*q]   - mu) * r * gg[2*q]   + bb[2*q];
                        float o1 = (h[2*q+1] - mu) * r * gg[2*q+1] + bb[2*q+1];
                        pk[q] = pack_h2(__float2half_rn(o0), __float2half_rn(o1));
                    }
                    uint2* xp = (uint2*)(sXn + tg * 136 + l16 * 8);
                    xp[0] = make_uint2(pk[0], pk[1]);
                    *(uint2*)(sXn + tg * 136 + l16 * 8 + 4) = make_uint2(pk[2], pk[3]);
                }
            }
        }
        if (l == NLAYER - 1) return;
        __syncthreads();                // xn ready; W1c0 in flight

        // ---------------- gemm1: hid = GELU(xn @ W1 + b1) ----------------
#pragma unroll 1
        for (int ch = 0; ch < 2; ch++) {
            CP_WAIT0();
            __syncthreads();            // W chunk visible to all
            float acc[2][4][4];
#pragma unroll
            for (int i = 0; i < 2; i++)
#pragma unroll
                for (int j = 0; j < 4; j++)
#pragma unroll
                    for (int q = 0; q < 4; q++) acc[i][j][q] = 0.f;
            gemm_tile<136>(sbXn, 0, sbW, acc, wm, wn, a_r, a_k, b_r, b_k);
            __syncthreads();            // all warps done reading sW
            // prefetch next chunk: ch==0 -> W1c1 ; ch==1 -> W2c0
            if (ch == 0) fill_w(sbW, w1l + (size_t)128 * D, D, tid);
            else         fill_w(sbW, w2l, HDIM, tid);
            // epilogue: bias + GELU -> sHid[:, ch*128 ..]
#pragma unroll
            for (int mi = 0; mi < 2; mi++)
#pragma unroll
                for (int nj = 0; nj < 4; nj++) {
                    int cc = wn + nj * 8 + 2 * t4;
                    float bv0 = __ldg(b1 + l * HDIM + ch * 128 + cc);
                    float bv1 = __ldg(b1 + l * HDIM + ch * 128 + cc + 1);
#pragma unroll
                    for (int hh = 0; hh < 2; hh++) {
                        int row = wm + mi * 16 + g + hh * 8;
                        float x0 = acc[mi][nj][2 * hh]     + bv0;
                        float x1 = acc[mi][nj][2 * hh + 1] + bv1;
                        float y0 = 0.5f * x0 * (1.0f + erff(x0 * 0.70710678118654752f));
                        float y1 = 0.5f * x1 * (1.0f + erff(x1 * 0.70710678118654752f));
                        *(uint32_t*)(sHid + row * 264 + ch * 128 + cc) =
                            pack_h2(__float2half_rn(y0), __float2half_rn(y1));
                    }
                }
        }
        __syncthreads();                // hid complete; W2c0 in flight

        // ---------------- gemm2: v = hid @ W2 + b2 ; partial += v --------
        {
            float acc[2][4][4];
#pragma unroll
            for (int i = 0; i < 2; i++)
#pragma unroll
                for (int j = 0; j < 4; j++)
#pragma unroll
                    for (int q = 0; q < 4; q++) acc[i][j][q] = 0.f;
#pragma unroll 1
            for (int kh = 0; kh < 2; kh++) {
                CP_WAIT0();
                __syncthreads();
                gemm_tile<264>(sbHid, kh * 128, sbW, acc, wm, wn, a_r, a_k, b_r, b_k);
                __syncthreads();
                if (kh == 0) fill_w(sbW, w2l + 128, HDIM, tid);   // W2 k-half 1
            }
            const int commit = ((l & 3) == 3);
            __half* cb = commit ? (&g_blocks[grp + 1][0] + (size_t)bm * D) : (__half*)0;
#pragma unroll
            for (int mi = 0; mi < 2; mi++)
#pragma unroll
                for (int nj = 0; nj < 4; nj++) {
                    int cc = wn + nj * 8 + 2 * t4;
                    float bv0 = __ldg(b2 + l * D + cc);
                    float bv1 = __ldg(b2 + l * D + cc + 1);
#pragma unroll
                    for (int hh = 0; hh < 2; hh++) {
                        int row = wm + mi * 16 + g + hh * 8;
                        float x0 = acc[mi][nj][2 * hh]     + bv0;
                        float x1 = acc[mi][nj][2 * hh + 1] + bv1;
                        float* pp = sPart + row * 128 + cc;
                        if (hasPartial) { x0 += pp[0]; x1 += pp[1]; }
                        pp[0] = x0; pp[1] = x1;
                        if (commit)
                            *(uint32_t*)(cb + (size_t)row * D + cc) =
                                pack_h2(__float2half_rn(x0), __float2half_rn(x1));
                    }
                }
        }
        __syncthreads();                // partial stable before next mix
    }
}

// ======================= prep: weights transpose + emb fp16 =================
__global__ void prep_all(const float* __restrict__ W1, const float* __restrict__ W2,
                         const float* __restrict__ emb) {
    const size_t T1 = (size_t)NLAYER * HDIM * D;
    const size_t T2 = (size_t)NLAYER * D * HDIM;
    const size_t T3 = (size_t)MTOK * D;
    for (size_t i = (size_t)blockIdx.x * blockDim.x + threadIdx.x; i < T1 + T2 + T3;
         i += (size_t)gridDim.x * blockDim.x) {
        if (i < T1) {
            size_t l = i / (HDIM * D), r = i % (HDIM * D);
            size_t n = r / D, k = r % D;
            g_w1t[i] = __float2half_rn(W1[(l * D + k) * HDIM + n]);
        } else if (i < T1 + T2) {
            size_t j = i - T1;
            size_t l = j / (D * HDIM), r = j % (D * HDIM);
            size_t n = r / HDIM, k = r % HDIM;
            g_w2t[j] = __float2half_rn(W2[(l * HDIM + k) * D + n]);
        } else {
            size_t j = i - T1 - T2;
            g_blocks[0][j] = __float2half_rn(emb[j]);
        }
    }
}

// ======================= host orchestration =================================
extern "C" void kernel_launch(void* const* d_in, const int* in_sizes, int n_in,
                              void* d_out, int out_size) {
    const float* emb  = (const float*)d_in[0];
    const float* w    = (const float*)d_in[1];
    const float* ln_g = (const float*)d_in[2];
    const float* ln_b = (const float*)d_in[3];
    const float* W1   = (const float*)d_in[4];
    const float* b1   = (const float*)d_in[5];
    const float* W2   = (const float*)d_in[6];
    const float* b2   = (const float*)d_in[7];
    float* out = (float*)d_out;

    cudaFuncSetAttribute(fused_net, cudaFuncAttributeMaxDynamicSharedMemorySize, SMEM_TOTAL);

    prep_all<<<512, 256>>>(W1, W2, emb);
    fused_net<<<NCTA, THREADS, SMEM_TOTAL>>>(w, ln_g, ln_b, b1, b2, out);
}

// round 9
// speedup vs baseline: 1.1435x; 1.0395x over previous
#include <cuda_runtime.h>
#include <cuda_fp16.h>
#include <math.h>
#include <stdint.h>

#define MTOK 65536   // 8 * 8192 tokens
#define D    128
#define HDIM 256
#define NLAYER 16
#define TTILE 128            // tokens per CTA
#define NCTA  (MTOK / TTILE) // 512
#define THREADS 512

// ======================= device global scratch ==============================
__device__ __half g_blocks[5][(size_t)MTOK * D];  // [0]=emb fp16, [1..4]=committed
__device__ __half g_w1t[NLAYER * HDIM * D];       // [l][n=256][k=128]
__device__ __half g_w2t[NLAYER * D * HDIM];       // [l][n=128][k=256]

// ======================= helpers ============================================
__device__ __forceinline__ uint32_t smem_u32(const void* p) {
    uint32_t a;
    asm("{ .reg .u64 t; cvta.to.shared.u64 t, %1; cvt.u32.u64 %0, t; }" : "=r"(a) : "l"(p));
    return a;
}
__device__ __forceinline__ uint32_t pack_h2(__half a, __half b) {
    return (uint32_t)__half_as_ushort(a) | ((uint32_t)__half_as_ushort(b) << 16);
}
__device__ __forceinline__ void ldm4(uint32_t* r, uint32_t addr) {
    asm volatile("ldmatrix.sync.aligned.m8n8.x4.shared.b16 {%0,%1,%2,%3}, [%4];"
                 : "=r"(r[0]), "=r"(r[1]), "=r"(r[2]), "=r"(r[3]) : "r"(addr));
}
__device__ __forceinline__ void mma16816(float* c, const uint32_t* a,
                                         uint32_t b0, uint32_t b1) {
    asm volatile("mma.sync.aligned.m16n8k16.row.col.f32.f16.f16.f32 "
                 "{%0,%1,%2,%3}, {%4,%5,%6,%7}, {%8,%9}, {%0,%1,%2,%3};"
                 : "+f"(c[0]), "+f"(c[1]), "+f"(c[2]), "+f"(c[3])
                 : "r"(a[0]), "r"(a[1]), "r"(a[2]), "r"(a[3]), "r"(b0), "r"(b1));
}
__device__ __forceinline__ void cp16(uint32_t dst, const void* src) {
    asm volatile("cp.async.cg.shared.global [%0], [%1], 16;" :: "r"(dst), "l"(src));
}
#define CP_COMMIT() asm volatile("cp.async.commit_group;" ::: "memory")
#define CP_WAIT0()  asm volatile("cp.async.wait_group 0;"  ::: "memory")

__device__ __forceinline__ float wsum16(float v) {
#pragma unroll
    for (int o = 8; o > 0; o >>= 1) v += __shfl_xor_sync(0xffffffffu, v, o);
    return v;
}

// ======================= smem layout ========================================
#define PSTRIDE 132                     // fp32 partial row stride (pad vs 128)
#define SP_PART 0                       // fp32 [128][132]          67584
#define SP_XN   67584                   // half [128][136]          34816
#define SP_HID  102400                  // half [128][136]          34816
#define SP_W0   137216                  // half [128][136]          34816
#define SP_W1   172032                  // half [128][136]          34816
#define SMEM_TOTAL 206848

// fill one 128x128-half weight chunk into dst (stride 136), rows from src with
// rowStride halves. 512 threads: 4 threads/row, 4x16B each. Ends with commit.
__device__ __forceinline__ void fill_w(uint32_t dst, const __half* __restrict__ src,
                                       int rowStride, int tid) {
    int row = tid >> 2, q = tid & 3;
    const char* s = (const char*)(src + (size_t)row * rowStride) + q * 64;
    uint32_t d = dst + (uint32_t)(row * 136 + q * 32) * 2;
#pragma unroll
    for (int j = 0; j < 4; j++) cp16(d + j * 16, s + j * 16);
    CP_COMMIT();
}

// 128x128x128 tile accumulation; A and B both stride 136 halves
__device__ __forceinline__ void gemm_tile(uint32_t sbA, uint32_t sbB,
                                          float acc[2][4][4], int wm, int wn,
                                          int a_r, int a_k, int b_r, int b_k) {
#pragma unroll
    for (int k16 = 0; k16 < 128; k16 += 16) {
        uint32_t a[2][4];
#pragma unroll
        for (int mi = 0; mi < 2; mi++)
            ldm4(a[mi], sbA + (uint32_t)((wm + mi * 16 + a_r) * 136 + k16 + a_k) * 2);
#pragma unroll
        for (int np = 0; np < 2; np++) {
            uint32_t t[4];
            ldm4(t, sbB + (uint32_t)((wn + np * 16 + b_r) * 136 + k16 + b_k) * 2);
            mma16816(acc[0][2 * np],     a[0], t[0], t[1]);
            mma16816(acc[0][2 * np + 1], a[0], t[2], t[3]);
            mma16816(acc[1][2 * np],     a[1], t[0], t[1]);
            mma16816(acc[1][2 * np + 1], a[1], t[2], t[3]);
        }
    }
}

#define ACC_CLEAR(acc)                                 \
    _Pragma("unroll") for (int i = 0; i < 2; i++)      \
    _Pragma("unroll") for (int j = 0; j < 4; j++)      \
    _Pragma("unroll") for (int q = 0; q < 4; q++) acc[i][j][q] = 0.f;

// ======================= fused whole-network kernel =========================
__global__ __launch_bounds__(THREADS, 1)
void fused_net(const float* __restrict__ w, const float* __restrict__ ln_g,
               const float* __restrict__ ln_b, const float* __restrict__ b1,
               const float* __restrict__ b2, float* __restrict__ out) {
    extern __shared__ char smem[];
    float*  sPart = (float*)(smem + SP_PART);
    __half* sXn   = (__half*)(smem + SP_XN);
    __half* sHid  = (__half*)(smem + SP_HID);
    const uint32_t sbXn  = smem_u32(sXn);
    const uint32_t sbHid = smem_u32(sHid);
    const uint32_t sbW0  = smem_u32(smem + SP_W0);
    const uint32_t sbW1  = smem_u32(smem + SP_W1);

    const int tid  = threadIdx.x;
    const int wid  = tid >> 5;
    const int lane = tid & 31;
    const int bm   = blockIdx.x * TTILE;

    // warp tiling: 16 warps = 4m x 4n, warp tile 32x32
    const int wm = (wid >> 2) * 32;
    const int wn = (wid & 3) * 32;
    const int a_r = (lane & 15);
    const int a_k = (lane >> 4) << 3;
    const int b_r = (lane & 7) + ((lane >> 4) << 3);
    const int b_k = ((lane >> 3) & 1) << 3;
    const int g  = lane >> 2;
    const int t4 = lane & 3;

    // mix coords: 16 lanes/token, 8 dims/lane, 32 tokens per pass
    const int mtok0 = tid >> 4;
    const int l16   = tid & 15;

    const __half* gb = &g_blocks[0][0];

    // prefetch layer-0 W1 chunk0
    fill_w(sbW0, g_w1t, D, tid);

    for (int l = 0; l < NLAYER; l++) {
        const int grp = l >> 2;
        const int hasPartial = (l & 3) != 0;
        const int nsg = 1 + grp;
        const __half* w1l = g_w1t + (size_t)l * HDIM * D;
        const __half* w2l = g_w2t + (size_t)l * D * HDIM;

        // ---------------- mix phase ----------------
        {
            const float* wrow = w + l * D;
            float wv[8], gg[8], bb[8];
            {
                float4 a0 = *(const float4*)(wrow + l16 * 8);
                float4 a1 = *(const float4*)(wrow + l16 * 8 + 4);
                wv[0]=a0.x; wv[1]=a0.y; wv[2]=a0.z; wv[3]=a0.w;
                wv[4]=a1.x; wv[5]=a1.y; wv[6]=a1.z; wv[7]=a1.w;
            }
            if (l < NLAYER - 1) {
                float4 a0 = *(const float4*)(ln_g + l * D + l16 * 8);
                float4 a1 = *(const float4*)(ln_g + l * D + l16 * 8 + 4);
                gg[0]=a0.x; gg[1]=a0.y; gg[2]=a0.z; gg[3]=a0.w;
                gg[4]=a1.x; gg[5]=a1.y; gg[6]=a1.z; gg[7]=a1.w;
                float4 c0 = *(const float4*)(ln_b + l * D + l16 * 8);
                float4 c1 = *(const float4*)(ln_b + l * D + l16 * 8 + 4);
                bb[0]=c0.x; bb[1]=c0.y; bb[2]=c0.z; bb[3]=c0.w;
                bb[4]=c1.x; bb[5]=c1.y; bb[6]=c1.z; bb[7]=c1.w;
            }
#pragma unroll 1
            for (int it = 0; it < 4; it++) {
                int tg = it * 32 + mtok0;
                float v[5][8];
                float lgt[5];
                int n = 0;
#pragma unroll
                for (int i = 0; i < 4; i++) {
                    if (i < nsg) {
                        uint4 raw = *(const uint4*)(gb + ((size_t)i * MTOK + bm + tg) * D + l16 * 8);
                        const uint32_t* pr = (const uint32_t*)&raw;
#pragma unroll
                        for (int q = 0; q < 4; q++) {
                            float2 f = __half22float2(*(const __half2*)&pr[q]);
                            v[i][2 * q] = f.x; v[i][2 * q + 1] = f.y;
                        }
                        n++;
                    }
                }
                if (hasPartial) {
                    const float* pp = sPart + tg * PSTRIDE + l16 * 8;
                    float4 p0 = *(const float4*)pp;
                    float4 p1 = *(const float4*)(pp + 4);
                    v[n][0]=p0.x; v[n][1]=p0.y; v[n][2]=p0.z; v[n][3]=p0.w;
                    v[n][4]=p1.x; v[n][5]=p1.y; v[n][6]=p1.z; v[n][7]=p1.w;
                    n++;
                }
#pragma unroll
                for (int i = 0; i < 5; i++) {
                    if (i < n) {
                        float ss = 0.f, dt = 0.f;
#pragma unroll
                        for (int j = 0; j < 8; j++) { ss += v[i][j]*v[i][j]; dt += wv[j]*v[i][j]; }
                        ss = wsum16(ss);
                        dt = wsum16(dt);
                        lgt[i] = dt * rsqrtf(ss * (1.0f / D) + 1e-8f);
                    }
                }
                float mx = -1e30f;
#pragma unroll
                for (int i = 0; i < 5; i++) if (i < n) mx = fmaxf(mx, lgt[i]);
                float se = 0.f;
#pragma unroll
                for (int i = 0; i < 5; i++) if (i < n) { lgt[i] = expf(lgt[i] - mx); se += lgt[i]; }
                float inv = 1.f / se;
                float h[8];
#pragma unroll
                for (int j = 0; j < 8; j++) h[j] = 0.f;
#pragma unroll
                for (int i = 0; i < 5; i++) if (i < n) {
                    float wt = lgt[i] * inv;
#pragma unroll
                    for (int j = 0; j < 8; j++) h[j] += wt * v[i][j];
                }

                if (l == NLAYER - 1) {
                    float* op = out + (size_t)(bm + tg) * D + l16 * 8;
                    float4 o0 = {h[0], h[1], h[2], h[3]};
                    float4 o1 = {h[4], h[5], h[6], h[7]};
                    *(float4*)op = o0;
                    *(float4*)(op + 4) = o1;
                } else {
                    float s = 0.f;
#pragma unroll
                    for (int j = 0; j < 8; j++) s += h[j];
                    float mu = wsum16(s) * (1.0f / D);
                    float vs = 0.f;
#pragma unroll
                    for (int j = 0; j < 8; j++) { float d0 = h[j] - mu; vs += d0 * d0; }
                    float var = wsum16(vs) * (1.0f / D);
                    float r = rsqrtf(var + 1e-5f);
                    uint32_t pk[4];
#pragma unroll
                    for (int q = 0; q < 4; q++) {
                        float o0 = (h[2*q]   - mu) * r * gg[2*q]   + bb[2*q];
                        float o1 = (h[2*q+1] - mu) * r * gg[2*q+1] + bb[2*q+1];
                        pk[q] = pack_h2(__float2half_rn(o0), __float2half_rn(o1));
                    }
                    *(uint2*)(sXn + tg * 136 + l16 * 8)     = make_uint2(pk[0], pk[1]);
                    *(uint2*)(sXn + tg * 136 + l16 * 8 + 4) = make_uint2(pk[2], pk[3]);
                }
            }
        }
        if (l == NLAYER - 1) return;

        float acc[2][4][4];

        // ===== Phase A: gemm1 ch0  (W1c0 in buf0) =====
        CP_WAIT0();
        __syncthreads();                       // buf0 ready, sXn visible
        fill_w(sbW1, w2l, HDIM, tid);          // prefetch W2 khalf0
        ACC_CLEAR(acc);
        gemm_tile(sbXn, sbW0, acc, wm, wn, a_r, a_k, b_r, b_k);
#pragma unroll
        for (int mi = 0; mi < 2; mi++)
#pragma unroll
            for (int nj = 0; nj < 4; nj++) {
                int cc = wn + nj * 8 + 2 * t4;
                float bv0 = __ldg(b1 + l * HDIM + cc);
                float bv1 = __ldg(b1 + l * HDIM + cc + 1);
#pragma unroll
                for (int hh = 0; hh < 2; hh++) {
                    int row = wm + mi * 16 + g + hh * 8;
                    float x0 = acc[mi][nj][2 * hh]     + bv0;
                    float x1 = acc[mi][nj][2 * hh + 1] + bv1;
                    float y0 = 0.5f * x0 * (1.0f + erff(x0 * 0.70710678118654752f));
                    float y1 = 0.5f * x1 * (1.0f + erff(x1 * 0.70710678118654752f));
                    *(uint32_t*)(sHid + row * 136 + cc) =
                        pack_h2(__float2half_rn(y0), __float2half_rn(y1));
                }
            }

        // ===== Phase B: gemm2 kh0  (W2k0 in buf1) =====
        CP_WAIT0();
        __syncthreads();                       // buf1 ready, sHid visible
        fill_w(sbW0, w1l + (size_t)128 * D, D, tid);   // prefetch W1 chunk1
        ACC_CLEAR(acc);
        gemm_tile(sbHid, sbW1, acc, wm, wn, a_r, a_k, b_r, b_k);
#pragma unroll
        for (int mi = 0; mi < 2; mi++)
#pragma unroll
            for (int nj = 0; nj < 4; nj++) {
                int cc = wn + nj * 8 + 2 * t4;
                float bv0 = __ldg(b2 + l * D + cc);
                float bv1 = __ldg(b2 + l * D + cc + 1);
#pragma unroll
                for (int hh = 0; hh < 2; hh++) {
                    int row = wm + mi * 16 + g + hh * 8;
                    float x0 = acc[mi][nj][2 * hh]     + bv0;
                    float x1 = acc[mi][nj][2 * hh + 1] + bv1;
                    float* pp = sPart + row * PSTRIDE + cc;
                    if (hasPartial) {
                        float2 o = *(const float2*)pp;
                        x0 += o.x; x1 += o.y;
                    }
                    float2 vv = {x0, x1};
                    *(float2*)pp = vv;
                }
            }

        // ===== Phase C: gemm1 ch1  (W1c1 in buf0) =====
        CP_WAIT0();
        __syncthreads();                       // buf0 ready, B done reading sHid
        fill_w(sbW1, w2l + 128, HDIM, tid);    // prefetch W2 khalf1
        ACC_CLEAR(acc);
        gemm_tile(sbXn, sbW0, acc, wm, wn, a_r, a_k, b_r, b_k);
#pragma unroll
        for (int mi = 0; mi < 2; mi++)
#pragma unroll
            for (int nj = 0; nj < 4; nj++) {
                int cc = wn + nj * 8 + 2 * t4;
                float bv0 = __ldg(b1 + l * HDIM + 128 + cc);
                float bv1 = __ldg(b1 + l * HDIM + 128 + cc + 1);
#pragma unroll
                for (int hh = 0; hh < 2; hh++) {
                    int row = wm + mi * 16 + g + hh * 8;
                    float x0 = acc[mi][nj][2 * hh]     + bv0;
                    float x1 = acc[mi][nj][2 * hh + 1] + bv1;
                    float y0 = 0.5f * x0 * (1.0f + erff(x0 * 0.70710678118654752f));
                    float y1 = 0.5f * x1 * (1.0f + erff(x1 * 0.70710678118654752f));
                    *(uint32_t*)(sHid + row * 136 + cc) =
                        pack_h2(__float2half_rn(y0), __float2half_rn(y1));
                }
            }

        // ===== Phase D: gemm2 kh1  (W2k1 in buf1) =====
        CP_WAIT0();
        __syncthreads();                       // buf1 ready, sHid(ch1) visible
        if (l < NLAYER - 2)
            fill_w(sbW0, g_w1t + (size_t)(l + 1) * HDIM * D, D, tid);  // next W1c0
        ACC_CLEAR(acc);
        gemm_tile(sbHid, sbW1, acc, wm, wn, a_r, a_k, b_r, b_k);
        {
            const int commit = ((l & 3) == 3);
            __half* cb = commit ? (&g_blocks[grp + 1][0] + (size_t)bm * D) : (__half*)0;
#pragma unroll
            for (int mi = 0; mi < 2; mi++)
#pragma unroll
                for (int nj = 0; nj < 4; nj++) {
                    int cc = wn + nj * 8 + 2 * t4;
#pragma unroll
                    for (int hh = 0; hh < 2; hh++) {
                        int row = wm + mi * 16 + g + hh * 8;
                        float* pp = sPart + row * PSTRIDE + cc;
                        float2 o = *(const float2*)pp;
                        float x0 = acc[mi][nj][2 * hh]     + o.x;
                        float x1 = acc[mi][nj][2 * hh + 1] + o.y;
                        float2 vv = {x0, x1};
                        *(float2*)pp = vv;
                        if (commit)
                            *(uint32_t*)(cb + (size_t)row * D + cc) =
                                pack_h2(__float2half_rn(x0), __float2half_rn(x1));
                    }
                }
        }
        __syncthreads();                       // sPart stable for next mix
    }
}

// ======================= prep: weights transpose + emb fp16 =================
__global__ void prep_all(const float* __restrict__ W1, const float* __restrict__ W2,
                         const float* __restrict__ emb) {
    const size_t T1 = (size_t)NLAYER * HDIM * D;
    const size_t T2 = (size_t)NLAYER * D * HDIM;
    const size_t T3 = (size_t)MTOK * D;
    for (size_t i = (size_t)blockIdx.x * blockDim.x + threadIdx.x; i < T1 + T2 + T3;
         i += (size_t)gridDim.x * blockDim.x) {
        if (i < T1) {
            size_t l = i / (HDIM * D), r = i % (HDIM * D);
            size_t n = r / D, k = r % D;
            g_w1t[i] = __float2half_rn(W1[(l * D + k) * HDIM + n]);
        } else if (i < T1 + T2) {
            size_t j = i - T1;
            size_t l = j / (D * HDIM), r = j % (D * HDIM);
            size_t n = r / HDIM, k = r % HDIM;
            g_w2t[j] = __float2half_rn(W2[(l * HDIM + k) * D + n]);
        } else {
            size_t j = i - T1 - T2;
            g_blocks[0][j] = __float2half_rn(emb[j]);
        }
    }
}

// ======================= host orchestration =================================
extern "C" void kernel_launch(void* const* d_in, const int* in_sizes, int n_in,
                              void* d_out, int out_size) {
    const float* emb  = (const float*)d_in[0];
    const float* w    = (const float*)d_in[1];
    const float* ln_g = (const float*)d_in[2];
    const float* ln_b = (const float*)d_in[3];
    const float* W1   = (const float*)d_in[4];
    const float* b1   = (const float*)d_in[5];
    const float* W2   = (const float*)d_in[6];
    const float* b2   = (const float*)d_in[7];
    float* out = (float*)d_out;

    cudaFuncSetAttribute(fused_net, cudaFuncAttributeMaxDynamicSharedMemorySize, SMEM_TOTAL);

    prep_all<<<512, 256>>>(W1, W2, emb);
    fused_net<<<NCTA, THREADS, SMEM_TOTAL>>>(w, ln_g, ln_b, b1, b2, out);
}

// round 10
// speedup vs baseline: 1.1547x; 1.0098x over previous
#include <cuda_runtime.h>
#include <cuda_fp16.h>
#include <math.h>
#include <stdint.h>

#define MTOK 65536   // 8 * 8192 tokens
#define D    128
#define HDIM 256
#define NLAYER 16
#define TTILE 128            // tokens per CTA
#define NCTA  (MTOK / TTILE) // 512
#define THREADS 512

// ======================= device global scratch ==============================
__device__ __half g_blocks[5][(size_t)MTOK * D];  // [0]=emb fp16, [1..4]=committed
__device__ __half g_w1t[NLAYER * HDIM * D];       // [l][n=256][k=128]
__device__ __half g_w2t[NLAYER * D * HDIM];       // [l][n=128][k=256]

// ======================= helpers ============================================
__device__ __forceinline__ uint32_t smem_u32(const void* p) {
    uint32_t a;
    asm("{ .reg .u64 t; cvta.to.shared.u64 t, %1; cvt.u32.u64 %0, t; }" : "=r"(a) : "l"(p));
    return a;
}
__device__ __forceinline__ uint32_t pack_h2(__half a, __half b) {
    return (uint32_t)__half_as_ushort(a) | ((uint32_t)__half_as_ushort(b) << 16);
}
__device__ __forceinline__ void ldm4(uint32_t* r, uint32_t addr) {
    asm volatile("ldmatrix.sync.aligned.m8n8.x4.shared.b16 {%0,%1,%2,%3}, [%4];"
                 : "=r"(r[0]), "=r"(r[1]), "=r"(r[2]), "=r"(r[3]) : "r"(addr));
}
__device__ __forceinline__ void mma16816(float* c, const uint32_t* a,
                                         uint32_t b0, uint32_t b1) {
    asm volatile("mma.sync.aligned.m16n8k16.row.col.f32.f16.f16.f32 "
                 "{%0,%1,%2,%3}, {%4,%5,%6,%7}, {%8,%9}, {%0,%1,%2,%3};"
                 : "+f"(c[0]), "+f"(c[1]), "+f"(c[2]), "+f"(c[3])
                 : "r"(a[0]), "r"(a[1]), "r"(a[2]), "r"(a[3]), "r"(b0), "r"(b1));
}
__device__ __forceinline__ void cp16(uint32_t dst, const void* src) {
    asm volatile("cp.async.cg.shared.global [%0], [%1], 16;" :: "r"(dst), "l"(src));
}
#define CP_COMMIT() asm volatile("cp.async.commit_group;" ::: "memory")
#define CP_WAIT0()  asm volatile("cp.async.wait_group 0;"  ::: "memory")

__device__ __forceinline__ float wsum16(float v) {
#pragma unroll
    for (int o = 8; o > 0; o >>= 1) v += __shfl_xor_sync(0xffffffffu, v, o);
    return v;
}

// Fast exact-GELU: branch-free A&S 7.1.26 erf (|abs err| <= 1.5e-7)
__device__ __forceinline__ float gelu_f(float x) {
    float z  = x * 0.70710678118654752f;
    float az = fabsf(z);
    float t  = __frcp_rn(fmaf(0.3275911f, az, 1.0f));
    float p  = fmaf(1.061405429f, t, -1.453152027f);
    p = fmaf(p, t, 1.421413741f);
    p = fmaf(p, t, -0.284496736f);
    p = fmaf(p, t, 0.254829592f);
    p = p * t;
    float e  = __expf(-z * z);
    float er = copysignf(fmaf(-p, e, 1.0f), z);
    return 0.5f * x * (1.0f + er);
}

// ======================= smem layout ========================================
#define PSTRIDE 132                     // fp32 partial row stride (pad vs 128)
#define SP_PART 0                       // fp32 [128][132]          67584
#define SP_XN   67584                   // half [128][136]          34816
#define SP_HID  102400                  // half [128][136]          34816
#define SP_W0   137216                  // half [128][136]          34816
#define SP_W1   172032                  // half [128][136]          34816
#define SP_INV  206848                  // fp32 [4][128]             2048
#define SMEM_TOTAL 208896

// fill one 128x128-half weight chunk into dst (stride 136)
__device__ __forceinline__ void fill_w(uint32_t dst, const __half* __restrict__ src,
                                       int rowStride, int tid) {
    int row = tid >> 2, q = tid & 3;
    const char* s = (const char*)(src + (size_t)row * rowStride) + q * 64;
    uint32_t d = dst + (uint32_t)(row * 136 + q * 32) * 2;
#pragma unroll
    for (int j = 0; j < 4; j++) cp16(d + j * 16, s + j * 16);
    CP_COMMIT();
}

// 128x128x128 tile accumulation; A and B both stride 136 halves
__device__ __forceinline__ void gemm_tile(uint32_t sbA, uint32_t sbB,
                                          float acc[2][4][4], int wm, int wn,
                                          int a_r, int a_k, int b_r, int b_k) {
#pragma unroll
    for (int k16 = 0; k16 < 128; k16 += 16) {
        uint32_t a[2][4];
#pragma unroll
        for (int mi = 0; mi < 2; mi++)
            ldm4(a[mi], sbA + (uint32_t)((wm + mi * 16 + a_r) * 136 + k16 + a_k) * 2);
#pragma unroll
        for (int np = 0; np < 2; np++) {
            uint32_t t[4];
            ldm4(t, sbB + (uint32_t)((wn + np * 16 + b_r) * 136 + k16 + b_k) * 2);
            mma16816(acc[0][2 * np],     a[0], t[0], t[1]);
            mma16816(acc[0][2 * np + 1], a[0], t[2], t[3]);
            mma16816(acc[1][2 * np],     a[1], t[0], t[1]);
            mma16816(acc[1][2 * np + 1], a[1], t[2], t[3]);
        }
    }
}

#define ACC_CLEAR(acc)                                 \
    _Pragma("unroll") for (int i = 0; i < 2; i++)      \
    _Pragma("unroll") for (int j = 0; j < 4; j++)      \
    _Pragma("unroll") for (int q = 0; q < 4; q++) acc[i][j][q] = 0.f;

// ======================= fused whole-network kernel =========================
__global__ __launch_bounds__(THREADS, 1)
void fused_net(const float* __restrict__ w, const float* __restrict__ ln_g,
               const float* __restrict__ ln_b, const float* __restrict__ b1,
               const float* __restrict__ b2, float* __restrict__ out) {
    extern __shared__ char smem[];
    float*  sPart = (float*)(smem + SP_PART);
    __half* sXn   = (__half*)(smem + SP_XN);
    __half* sHid  = (__half*)(smem + SP_HID);
    float*  sInv  = (float*)(smem + SP_INV);
    const uint32_t sbXn  = smem_u32(sXn);
    const uint32_t sbHid = smem_u32(sHid);
    const uint32_t sbW0  = smem_u32(smem + SP_W0);
    const uint32_t sbW1  = smem_u32(smem + SP_W1);

    const int tid  = threadIdx.x;
    const int wid  = tid >> 5;
    const int lane = tid & 31;
    const int bm   = blockIdx.x * TTILE;

    // warp tiling: 16 warps = 4m x 4n, warp tile 32x32
    const int wm = (wid >> 2) * 32;
    const int wn = (wid & 3) * 32;
    const int a_r = (lane & 15);
    const int a_k = (lane >> 4) << 3;
    const int b_r = (lane & 7) + ((lane >> 4) << 3);
    const int b_k = ((lane >> 3) & 1) << 3;
    const int g  = lane >> 2;
    const int t4 = lane & 3;

    // mix coords: 16 lanes/token, 8 dims/lane, 32 tokens per pass
    const int mtok0 = tid >> 4;
    const int l16   = tid & 15;

    const __half* gb = &g_blocks[0][0];

    // prefetch layer-0 W1 chunk0
    fill_w(sbW0, g_w1t, D, tid);

    for (int l = 0; l < NLAYER; l++) {
        const int grp = l >> 2;
        const int hasPartial = (l & 3) != 0;
        const int nsg = 1 + grp;
        const __half* w1l = g_w1t + (size_t)l * HDIM * D;
        const __half* w2l = g_w2t + (size_t)l * D * HDIM;

        // ---------------- mix phase ----------------
        {
            const float* wrow = w + l * D;
            float wv[8], gg[8], bb[8];
            {
                float4 a0 = *(const float4*)(wrow + l16 * 8);
                float4 a1 = *(const float4*)(wrow + l16 * 8 + 4);
                wv[0]=a0.x; wv[1]=a0.y; wv[2]=a0.z; wv[3]=a0.w;
                wv[4]=a1.x; wv[5]=a1.y; wv[6]=a1.z; wv[7]=a1.w;
            }
            if (l < NLAYER - 1) {
                float4 a0 = *(const float4*)(ln_g + l * D + l16 * 8);
                float4 a1 = *(const float4*)(ln_g + l * D + l16 * 8 + 4);
                gg[0]=a0.x; gg[1]=a0.y; gg[2]=a0.z; gg[3]=a0.w;
                gg[4]=a1.x; gg[5]=a1.y; gg[6]=a1.z; gg[7]=a1.w;
                float4 c0 = *(const float4*)(ln_b + l * D + l16 * 8);
                float4 c1 = *(const float4*)(ln_b + l * D + l16 * 8 + 4);
                bb[0]=c0.x; bb[1]=c0.y; bb[2]=c0.z; bb[3]=c0.w;
                bb[4]=c1.x; bb[5]=c1.y; bb[6]=c1.z; bb[7]=c1.w;
            }
#pragma unroll 1
            for (int it = 0; it < 4; it++) {
                int tg = it * 32 + mtok0;
                float v[5][8];
                float lgt[5];
                int n = 0;
#pragma unroll
                for (int i = 0; i < 4; i++) {
                    if (i < nsg) {
                        uint4 raw = *(const uint4*)(gb + ((size_t)i * MTOK + bm + tg) * D + l16 * 8);
                        const uint32_t* pr = (const uint32_t*)&raw;
#pragma unroll
                        for (int q = 0; q < 4; q++) {
                            float2 f = __half22float2(*(const __half2*)&pr[q]);
                            v[i][2 * q] = f.x; v[i][2 * q + 1] = f.y;
                        }
                        float dt = 0.f;
#pragma unroll
                        for (int j = 0; j < 8; j++) dt += wv[j] * v[i][j];
                        float dtr = wsum16(dt);
                        float ir;
                        if (l == 4 * i) {           // source is new: compute + cache
                            float ss = 0.f;
#pragma unroll
                            for (int j = 0; j < 8; j++) ss += v[i][j] * v[i][j];
                            ss = wsum16(ss);
                            ir = rsqrtf(ss * (1.0f / D) + 1e-8f);
                            if (l16 == 0) sInv[i * 128 + tg] = ir;
                        } else {
                            ir = sInv[i * 128 + tg];
                        }
                        lgt[i] = dtr * ir;
                        n++;
                    }
                }
                if (hasPartial) {
                    const float* pp = sPart + tg * PSTRIDE + l16 * 8;
                    float4 p0 = *(const float4*)pp;
                    float4 p1 = *(const float4*)(pp + 4);
                    v[n][0]=p0.x; v[n][1]=p0.y; v[n][2]=p0.z; v[n][3]=p0.w;
                    v[n][4]=p1.x; v[n][5]=p1.y; v[n][6]=p1.z; v[n][7]=p1.w;
                    float ss = 0.f, dt = 0.f;
#pragma unroll
                    for (int j = 0; j < 8; j++) { ss += v[n][j]*v[n][j]; dt += wv[j]*v[n][j]; }
                    ss = wsum16(ss);
                    dt = wsum16(dt);
                    lgt[n] = dt * rsqrtf(ss * (1.0f / D) + 1e-8f);
                    n++;
                }
                float mx = -1e30f;
#pragma unroll
                for (int i = 0; i < 5; i++) if (i < n) mx = fmaxf(mx, lgt[i]);
                float se = 0.f;
#pragma unroll
                for (int i = 0; i < 5; i++) if (i < n) { lgt[i] = __expf(lgt[i] - mx); se += lgt[i]; }
                float inv = __frcp_rn(se);
                float h[8];
#pragma unroll
                for (int j = 0; j < 8; j++) h[j] = 0.f;
#pragma unroll
                for (int i = 0; i < 5; i++) if (i < n) {
                    float wt = lgt[i] * inv;
#pragma unroll
                    for (int j = 0; j < 8; j++) h[j] += wt * v[i][j];
                }

                if (l == NLAYER - 1) {
                    float* op = out + (size_t)(bm + tg) * D + l16 * 8;
                    float4 o0 = {h[0], h[1], h[2], h[3]};
                    float4 o1 = {h[4], h[5], h[6], h[7]};
                    *(float4*)op = o0;
                    *(float4*)(op + 4) = o1;
                } else {
                    float s = 0.f;
#pragma unroll
                    for (int j = 0; j < 8; j++) s += h[j];
                    float mu = wsum16(s) * (1.0f / D);
                    float vs = 0.f;
#pragma unroll
                    for (int j = 0; j < 8; j++) { float d0 = h[j] - mu; vs += d0 * d0; }
                    float var = wsum16(vs) * (1.0f / D);
                    float r = rsqrtf(var + 1e-5f);
                    uint32_t pk[4];
#pragma unroll
                    for (int q = 0; q < 4; q++) {
                        float o0 = (h[2*q]   - mu) * r * gg[2*q]   + bb[2*q];
                        float o1 = (h[2*q+1] - mu) * r * gg[2*q+1] + bb[2*q+1];
                        pk[q] = pack_h2(__float2half_rn(o0), __float2half_rn(o1));
                    }
                    *(uint2*)(sXn + tg * 136 + l16 * 8)     = make_uint2(pk[0], pk[1]);
                    *(uint2*)(sXn + tg * 136 + l16 * 8 + 4) = make_uint2(pk[2], pk[3]);
                }
            }
        }
        if (l == NLAYER - 1) return;

        float acc[2][4][4];

        // ===== Phase A: gemm1 ch0  (W1c0 in buf0) =====
        CP_WAIT0();
        __syncthreads();
        fill_w(sbW1, w2l, HDIM, tid);          // prefetch W2 khalf0
        ACC_CLEAR(acc);
        gemm_tile(sbXn, sbW0, acc, wm, wn, a_r, a_k, b_r, b_k);
#pragma unroll
        for (int mi = 0; mi < 2; mi++)
#pragma unroll
            for (int nj = 0; nj < 4; nj++) {
                int cc = wn + nj * 8 + 2 * t4;
                float bv0 = __ldg(b1 + l * HDIM + cc);
                float bv1 = __ldg(b1 + l * HDIM + cc + 1);
#pragma unroll
                for (int hh = 0; hh < 2; hh++) {
                    int row = wm + mi * 16 + g + hh * 8;
                    float y0 = gelu_f(acc[mi][nj][2 * hh]     + bv0);
                    float y1 = gelu_f(acc[mi][nj][2 * hh + 1] + bv1);
                    *(uint32_t*)(sHid + row * 136 + cc) =
                        pack_h2(__float2half_rn(y0), __float2half_rn(y1));
                }
            }

        // ===== Phase B: gemm2 kh0  (W2k0 in buf1) =====
        CP_WAIT0();
        __syncthreads();
        fill_w(sbW0, w1l + (size_t)128 * D, D, tid);   // prefetch W1 chunk1
        ACC_CLEAR(acc);
        gemm_tile(sbHid, sbW1, acc, wm, wn, a_r, a_k, b_r, b_k);
#pragma unroll
        for (int mi = 0; mi < 2; mi++)
#pragma unroll
            for (int nj = 0; nj < 4; nj++) {
                int cc = wn + nj * 8 + 2 * t4;
                float bv0 = __ldg(b2 + l * D + cc);
                float bv1 = __ldg(b2 + l * D + cc + 1);
#pragma unroll
                for (int hh = 0; hh < 2; hh++) {
                    int row = wm + mi * 16 + g + hh * 8;
                    float x0 = acc[mi][nj][2 * hh]     + bv0;
                    float x1 = acc[mi][nj][2 * hh + 1] + bv1;
                    float* pp = sPart + row * PSTRIDE + cc;
                    if (hasPartial) {
                        float2 o = *(const float2*)pp;
                        x0 += o.x; x1 += o.y;
                    }
                    float2 vv = {x0, x1};
                    *(float2*)pp = vv;
                }
            }

        // ===== Phase C: gemm1 ch1  (W1c1 in buf0) =====
        CP_WAIT0();
        __syncthreads();
        fill_w(sbW1, w2l + 128, HDIM, tid);    // prefetch W2 khalf1
        ACC_CLEAR(acc);
        gemm_tile(sbXn, sbW0, acc, wm, wn, a_r, a_k, b_r, b_k);
#pragma unroll
        for (int mi = 0; mi < 2; mi++)
#pragma unroll
            for (int nj = 0; nj < 4; nj++) {
                int cc = wn + nj * 8 + 2 * t4;
                float bv0 = __ldg(b1 + l * HDIM + 128 + cc);
                float bv1 = __ldg(b1 + l * HDIM + 128 + cc + 1);
#pragma unroll
                for (int hh = 0; hh < 2; hh++) {
                    int row = wm + mi * 16 + g + hh * 8;
                    float y0 = gelu_f(acc[mi][nj][2 * hh]     + bv0);
                    float y1 = gelu_f(acc[mi][nj][2 * hh + 1] + bv1);
                    *(uint32_t*)(sHid + row * 136 + cc) =
                        pack_h2(__float2half_rn(y0), __float2half_rn(y1));
                }
            }

        // ===== Phase D: gemm2 kh1  (W2k1 in buf1) =====
        CP_WAIT0();
        __syncthreads();
        if (l < NLAYER - 2)
            fill_w(sbW0, g_w1t + (size_t)(l + 1) * HDIM * D, D, tid);  // next W1c0
        ACC_CLEAR(acc);
        gemm_tile(sbHid, sbW1, acc, wm, wn, a_r, a_k, b_r, b_k);
        {
            const int commit = ((l & 3) == 3);
            __half* cb = commit ? (&g_blocks[grp + 1][0] + (size_t)bm * D) : (__half*)0;
#pragma unroll
            for (int mi = 0; mi < 2; mi++)
#pragma unroll
                for (int nj = 0; nj < 4; nj++) {
                    int cc = wn + nj * 8 + 2 * t4;
#pragma unroll
                    for (int hh = 0; hh < 2; hh++) {
                        int row = wm + mi * 16 + g + hh * 8;
                        float* pp = sPart + row * PSTRIDE + cc;
                        float2 o = *(const float2*)pp;
                        float x0 = acc[mi][nj][2 * hh]     + o.x;
                        float x1 = acc[mi][nj][2 * hh + 1] + o.y;
                        float2 vv = {x0, x1};
                        *(float2*)pp = vv;
                        if (commit)
                            *(uint32_t*)(cb + (size_t)row * D + cc) =
                                pack_h2(__float2half_rn(x0), __float2half_rn(x1));
                    }
                }
        }
        __syncthreads();
    }
}

// ======================= prep kernels =======================================
// Coalesced 32x32 smem-tiled transpose + fp32->fp16 for W1/W2.
__global__ void transpose_w(const float* __restrict__ W1, const float* __restrict__ W2) {
    __shared__ float tile[32][33];
    int b = blockIdx.x;              // 16 layers * 64 tiles
    int lay = b >> 6, t = b & 63;
    const float* in;
    __half* outp;
    int inC, outC, tr, tc;
    if (t < 32) {                    // W1: in [128][256] -> out [256][128]
        in = W1 + (size_t)lay * D * HDIM;
        outp = g_w1t + (size_t)lay * HDIM * D;
        inC = HDIM; outC = D;
        tr = t >> 3; tc = t & 7;
    } else {                         // W2: in [256][128] -> out [128][256]
        int tt = t - 32;
        in = W2 + (size_t)lay * HDIM * D;
        outp = g_w2t + (size_t)lay * D * HDIM;
        inC = D; outC = HDIM;
        tr = tt >> 2; tc = tt & 3;
    }
    int x = threadIdx.x, y = threadIdx.y;    // (32, 8)
#pragma unroll
    for (int yy = 0; yy < 4; yy++) {
        int r = y * 4 + yy;
        tile[r][x] = in[(size_t)(tr * 32 + r) * inC + tc * 32 + x];
    }
    __syncthreads();
#pragma unroll
    for (int yy = 0; yy < 4; yy++) {
        int r = y * 4 + yy;
        outp[(size_t)(tc * 32 + r) * outC + tr * 32 + x] = __float2half_rn(tile[x][r]);
    }
}

__global__ void conv_emb(const float* __restrict__ emb) {
    const size_t N = (size_t)MTOK * D;
    for (size_t i = (size_t)blockIdx.x * blockDim.x + threadIdx.x; i < N;
         i += (size_t)gridDim.x * blockDim.x)
        g_blocks[0][i] = __float2half_rn(emb[i]);
}

// ======================= host orchestration =================================
extern "C" void kernel_launch(void* const* d_in, const int* in_sizes, int n_in,
                              void* d_out, int out_size) {
    const float* emb  = (const float*)d_in[0];
    const float* w    = (const float*)d_in[1];
    const float* ln_g = (const float*)d_in[2];
    const float* ln_b = (const float*)d_in[3];
    const float* W1   = (const float*)d_in[4];
    const float* b1   = (const float*)d_in[5];
    const float* W2   = (const float*)d_in[6];
    const float* b2   = (const float*)d_in[7];
    float* out = (float*)d_out;

    cudaFuncSetAttribute(fused_net, cudaFuncAttributeMaxDynamicSharedMemorySize, SMEM_TOTAL);

    transpose_w<<<NLAYER * 64, dim3(32, 8)>>>(W1, W2);
    conv_emb<<<512, 256>>>(emb);
    fused_net<<<NCTA, THREADS, SMEM_TOTAL>>>(w, ln_g, ln_b, b1, b2, out);
}